// round 1
// baseline (speedup 1.0000x reference)
#include <cuda_runtime.h>

#define D      128
#define K      64
#define N_MAX  200000
#define TEMP   30.0f
#define EPSn   1e-6f
#define CHUNK  32
#define ITERS  11
#define SMEM_BYTES ((D*K + CHUNK*D + CHUNK*K) * 4)

// Scratch (no allocation allowed in kernel_launch)
__device__ float g_dataN[(size_t)N_MAX * D];  // normalized data, 102.4 MB
__device__ float g_muT[D * K];                // normalized mu, transposed [d][k]
__device__ float g_mean[K * D];               // cluster_mean accumulator
__device__ float g_cnt[K];                    // cluster_r accumulator

// ---------------------------------------------------------------------------
// One warp per row: normalize data rows once.
__global__ void norm_data_kernel(const float* __restrict__ x, int N) {
    int w = (blockIdx.x * blockDim.x + threadIdx.x) >> 5;
    int lane = threadIdx.x & 31;
    if (w >= N) return;
    const float4* row = (const float4*)(x + (size_t)w * D);
    float4 v = row[lane];
    float ss = v.x*v.x + v.y*v.y + v.z*v.z + v.w*v.w;
    #pragma unroll
    for (int o = 16; o > 0; o >>= 1) ss += __shfl_xor_sync(0xffffffffu, ss, o);
    float inv = 1.0f / (sqrtf(ss) + EPSn);
    float4 o4 = make_float4(v.x*inv, v.y*inv, v.z*inv, v.w*inv);
    ((float4*)(g_dataN + (size_t)w * D))[lane] = o4;
}

// ---------------------------------------------------------------------------
// Normalize init mu -> g_muT, zero accumulators. grid=K, block=128.
__global__ void init_mu_kernel(const float* __restrict__ init) {
    int k = blockIdx.x;
    int d = threadIdx.x;
    float v = init[k * D + d];
    __shared__ float sred[4];
    float ss = v * v;
    #pragma unroll
    for (int o = 16; o > 0; o >>= 1) ss += __shfl_xor_sync(0xffffffffu, ss, o);
    if ((d & 31) == 0) sred[d >> 5] = ss;
    __syncthreads();
    float tot = sred[0] + sred[1] + sred[2] + sred[3];
    g_muT[d * K + k] = v / (sqrtf(tot) + EPSn);
    g_mean[k * D + d] = 0.0f;
    if (d == 0) g_cnt[k] = 0.0f;
}

// ---------------------------------------------------------------------------
// Fused iteration: dist = dataN @ muT, softmax(TEMP*dist), accumulate
// cluster_r and r^T @ dataN. Optionally writes r to global (last iteration).
// block = 256 threads (8 warps), dynamic smem = 56 KB, grid-strided over
// 32-row chunks.
template<bool WRITE_R>
__global__ void __launch_bounds__(256, 2) iter_kernel(float* __restrict__ r_out,
                                                      int nChunks) {
    extern __shared__ float sm[];
    float* sMuT  = sm;                  // [128][64]
    float* sData = sm + D * K;          // [32][128]
    float* sR    = sData + CHUNK * D;   // [32][64]

    int tid = threadIdx.x;
    int w = tid >> 5, l = tid & 31;

    // stage muT (32 KB)
    #pragma unroll
    for (int i = tid; i < D * K / 4; i += 256)
        ((float4*)sMuT)[i] = ((const float4*)g_muT)[i];

    // phase-C ownership: thread owns cluster kIdx and a 32-wide d-slice
    int kIdx = ((w & 1) << 5) + l;
    int dblk = w >> 1;
    float acc[32];
    #pragma unroll
    for (int j = 0; j < 32; j++) acc[j] = 0.0f;
    float cacc = 0.0f;

    __syncthreads();

    for (int c = blockIdx.x; c < nChunks; c += gridDim.x) {
        // ---- phase A: stage 32 data rows (16 KB) ----
        const float4* src = (const float4*)(g_dataN + (size_t)c * CHUNK * D);
        #pragma unroll
        for (int i = 0; i < 4; i++)
            ((float4*)sData)[tid + 256 * i] = src[tid + 256 * i];
        __syncthreads();

        // ---- phase B: dist + softmax. warp w -> rows 4w..4w+3,
        //      lane l -> clusters 2l, 2l+1 ----
        float ax[4], ay[4];
        #pragma unroll
        for (int i = 0; i < 4; i++) { ax[i] = 0.0f; ay[i] = 0.0f; }
        const float* base = sData + (w * 4) * D;
        #pragma unroll 4
        for (int d = 0; d < D; d++) {
            float2 m = *(const float2*)(sMuT + d * K + 2 * l);
            #pragma unroll
            for (int i = 0; i < 4; i++) {
                float x = base[i * D + d];
                ax[i] += x * m.x;
                ay[i] += x * m.y;
            }
        }
        #pragma unroll
        for (int i = 0; i < 4; i++) {
            float tx = TEMP * ax[i], ty = TEMP * ay[i];
            float mx = fmaxf(tx, ty);
            #pragma unroll
            for (int o = 16; o > 0; o >>= 1)
                mx = fmaxf(mx, __shfl_xor_sync(0xffffffffu, mx, o));
            float ex = __expf(tx - mx), ey = __expf(ty - mx);
            float s = ex + ey;
            #pragma unroll
            for (int o = 16; o > 0; o >>= 1)
                s += __shfl_xor_sync(0xffffffffu, s, o);
            float invs = 1.0f / s;
            float2 rv = make_float2(ex * invs, ey * invs);
            *(float2*)(sR + (w * 4 + i) * K + 2 * l) = rv;
        }
        __syncthreads();

        if (WRITE_R) {
            float4* dst = (float4*)(r_out + (size_t)c * CHUNK * K);
            #pragma unroll
            for (int i = 0; i < 2; i++)
                dst[tid + 256 * i] = ((const float4*)sR)[tid + 256 * i];
        }

        // ---- phase C: acc[kIdx][dblk*32 + j] += r[n][kIdx] * data[n][...] ----
        const float* dcol = sData + dblk * 32;
        #pragma unroll 4
        for (int n = 0; n < CHUNK; n++) {
            float rv = sR[n * K + kIdx];
            cacc += rv;
            const float4* dp = (const float4*)(dcol + n * D);
            #pragma unroll
            for (int j = 0; j < 8; j++) {
                float4 v = dp[j];
                acc[4 * j + 0] += rv * v.x;
                acc[4 * j + 1] += rv * v.y;
                acc[4 * j + 2] += rv * v.z;
                acc[4 * j + 3] += rv * v.w;
            }
        }
        __syncthreads();
    }

    // flush partials
    float* gm = g_mean + kIdx * D + dblk * 32;
    #pragma unroll
    for (int j = 0; j < 32; j++) atomicAdd(gm + j, acc[j]);
    if (dblk == 0) atomicAdd(&g_cnt[kIdx], cacc);
}

// ---------------------------------------------------------------------------
// mu = mean / cnt; if not last: normalize + transpose into g_muT; zero accs.
// grid=K, block=128.
__global__ void update_kernel(int last, float* __restrict__ mu_out) {
    int k = blockIdx.x;
    int d = threadIdx.x;
    float cnt = g_cnt[k];
    float v = g_mean[k * D + d] / cnt;
    __shared__ float sred[4];
    float ss = v * v;
    #pragma unroll
    for (int o = 16; o > 0; o >>= 1) ss += __shfl_xor_sync(0xffffffffu, ss, o);
    if ((d & 31) == 0) sred[d >> 5] = ss;
    __syncthreads();   // also guarantees g_cnt[k] fully read before zeroing
    float tot = sred[0] + sred[1] + sred[2] + sred[3];
    if (last) {
        mu_out[k * D + d] = v;
    } else {
        g_muT[d * K + k] = v / (sqrtf(tot) + EPSn);
    }
    g_mean[k * D + d] = 0.0f;
    if (d == 0) g_cnt[k] = 0.0f;
}

// ---------------------------------------------------------------------------
extern "C" void kernel_launch(void* const* d_in, const int* in_sizes, int n_in,
                              void* d_out, int out_size) {
    const float* embeds = (const float*)d_in[0];
    const float* init   = (const float*)d_in[1];
    int N = in_sizes[0] / D;
    int nChunks = (N + CHUNK - 1) / CHUNK;
    float* out_mu = (float*)d_out;
    float* out_r  = (float*)d_out + K * D;

    // Opt-in for 56 KB dynamic smem (idempotent; not a stream op).
    cudaFuncSetAttribute(iter_kernel<false>,
                         cudaFuncAttributeMaxDynamicSharedMemorySize, SMEM_BYTES);
    cudaFuncSetAttribute(iter_kernel<true>,
                         cudaFuncAttributeMaxDynamicSharedMemorySize, SMEM_BYTES);

    norm_data_kernel<<<(N + 7) / 8, 256>>>(embeds, N);
    init_mu_kernel<<<K, 128>>>(init);

    for (int it = 0; it < ITERS; it++) {
        int last = (it == ITERS - 1);
        if (last)
            iter_kernel<true><<<296, 256, SMEM_BYTES>>>(out_r, nChunks);
        else
            iter_kernel<false><<<296, 256, SMEM_BYTES>>>(nullptr, nChunks);
        update_kernel<<<K, 128>>>(last, out_mu);
    }
}